// round 2
// baseline (speedup 1.0000x reference)
#include <cuda_runtime.h>

#define NBLK   10
#define NBATCH 2048
#define NCH    64
#define NSKIP  96
#define TILE   16
#define NCOLS  1023
#define CURP   68                      /* padded row stride for cur/del/z */
#define SSP    100                     /* padded row stride for skip/h */
#define REGF   (TILE*NCH*NCOLS)        /* 1047552 floats per CTA region */
#define NC32   (REGF/32)               /* 32736 chunks of 32 floats */

#define FMA4(acc, s, v) do { (acc)[0] += (s)*(v).x; (acc)[1] += (s)*(v).y; \
                             (acc)[2] += (s)*(v).z; (acc)[3] += (s)*(v).w; } while(0)

#define CBAR() asm volatile("bar.sync 1, 256;" ::: "memory")

// ---------------------------------------------------------------------------
// Fused kernel: 128 CTAs x 384 threads.
//   threads 0..255  : compute (16 samples, thread = 1 sample x 4 channels)
//   threads 256..383: shift of this CTA's own 1024 buffer rows (4.19 MB)
// After the final block-wide barrier, all threads scatter the 10 insertion
// columns (snapshots were parked in the dead del[i] smem slots).
// ---------------------------------------------------------------------------
__global__ __launch_bounds__(384, 1) void wn_fused(
    const float* __restrict__ x,   const float* __restrict__ buf,
    const float* __restrict__ inp_w, const float* __restrict__ inp_b,
    const float* __restrict__ fw0, const float* __restrict__ fw1, const float* __restrict__ fb,
    const float* __restrict__ gw0, const float* __restrict__ gw1, const float* __restrict__ gb,
    const float* __restrict__ rw,  const float* __restrict__ rb,
    const float* __restrict__ sw,  const float* __restrict__ sb,
    const float* __restrict__ h1w, const float* __restrict__ h1b,
    const float* __restrict__ h2w, const float* __restrict__ h2b,
    float* __restrict__ out, float* __restrict__ nbuf)
{
    extern __shared__ float sm[];
    float* cur = sm;                          // 16*68
    float* zs  = cur + TILE*CURP;             // 16*68 (x tile, then z)
    float* del = zs  + TILE*CURP;             // 10*16*68 (taps, then snapshots)
    float* w0  = del + NBLK*TILE*CURP;        // 4096 transposed [k][t]
    float* w1  = w0 + 4096;
    float* w2  = w1 + 4096;
    float* w3  = w2 + 4096;
    float* wrs = w3 + 4096;
    float* wst = wrs + 4096;                  // 64*96 skip weights transposed
    float* bia = wst + 6144;                  // fb[64] gb[64] rb[64] sb[96]
    float* ssm = bia + 288;                   // 16*100
    float* hsm = ssm + TILE*SSP;              // 16*100

    const int tid   = threadIdx.x;
    const int lane  = tid & 31;
    const int bbase = blockIdx.x * TILE;
    const size_t region = (size_t)blockIdx.x * REGF;

    if (tid < 256) {
        // =================== COMPUTE GROUP (256 threads) ===================
        const int sp = tid >> 4, tg = tid & 15;
        const int t0 = tg * 4, ts = tg * 6;

        // ---- x tile (16 x 32) into zs scratch ----
        for (int idx = tid; idx < TILE*32; idx += 256)
            zs[idx] = x[(bbase + (idx >> 5))*32 + (idx & 31)];

        // ---- preload all delayed taps: del[i][s][c] = buf[b,c,2^i-1] ----
        for (int idx = tid; idx < NBLK*TILE*NCH; idx += 256) {
            int i = idx >> 10, r = idx & 1023;
            int s = r >> 6, c = r & 63;
            int off = (1 << i) - 1;
            del[(i*TILE + s)*CURP + c] =
                buf[((size_t)(bbase + s)*NCH + c)*NCOLS + off];
        }
        CBAR();

        // ---- input projection: cur = x @ inp_w.T + inp_b ----
        {
            float a[4];
            #pragma unroll
            for (int j = 0; j < 4; ++j) a[j] = inp_b[t0 + j];
            #pragma unroll 8
            for (int k = 0; k < 32; ++k) {
                float xk = zs[sp*32 + k];
                #pragma unroll
                for (int j = 0; j < 4; ++j)
                    a[j] += xk * inp_w[(t0 + j)*32 + k];
            }
            #pragma unroll
            for (int j = 0; j < 4; ++j) cur[sp*CURP + t0 + j] = a[j];
        }

        float ssum[6];
        #pragma unroll
        for (int j = 0; j < 6; ++j) ssum[j] = 0.f;

        for (int i = 0; i < NBLK; ++i) {
            CBAR();   // prev iter fully done with weights / cur updates visible

            // ---- stage transposed weights for this block ----
            {
                const float* srcs[5] = { fw0 + i*4096, fw1 + i*4096, gw0 + i*4096,
                                         gw1 + i*4096, rw + i*4096 };
                float* dsts[5] = { w0, w1, w2, w3, wrs };
                #pragma unroll
                for (int mm = 0; mm < 5; ++mm) {
                    const float* s = srcs[mm]; float* d = dsts[mm];
                    #pragma unroll
                    for (int it = 0; it < 4; ++it) {
                        int idx = it*256 + tid;           // 1024 float4 total
                        int q = idx >> 6, t = idx & 63;
                        float4 v = *(const float4*)(s + t*64 + q*4);
                        d[(4*q+0)*64+t] = v.x; d[(4*q+1)*64+t] = v.y;
                        d[(4*q+2)*64+t] = v.z; d[(4*q+3)*64+t] = v.w;
                    }
                }
                const float* s = sw + i*NSKIP*NCH;        // [96][64] -> wst[64][96]
                #pragma unroll
                for (int it = 0; it < 6; ++it) {
                    int idx = it*256 + tid;               // 1536 float4 total
                    int q = idx / 96, t = idx - q*96;
                    float4 v = *(const float4*)(s + t*64 + q*4);
                    wst[(4*q+0)*96+t] = v.x; wst[(4*q+1)*96+t] = v.y;
                    wst[(4*q+2)*96+t] = v.z; wst[(4*q+3)*96+t] = v.w;
                }
                if (tid < 64) {
                    bia[tid]     = fb[i*64 + tid];
                    bia[64+tid]  = gb[i*64 + tid];
                    bia[128+tid] = rb[i*64 + tid];
                }
                if (tid < 96) bia[192 + tid] = sb[i*NSKIP + tid];
            }
            CBAR();

            // ---- f/g GEMMs ----
            float f[4], g[4];
            #pragma unroll
            for (int j = 0; j < 4; ++j) { f[j] = bia[t0+j]; g[j] = bia[64+t0+j]; }
            const float* dle = del + i*TILE*CURP + sp*CURP;
            const float* cu  = cur + sp*CURP;
            #pragma unroll 8
            for (int k = 0; k < 64; ++k) {
                float dk = dle[k], ck = cu[k];
                float4 wa = *(const float4*)(w0 + k*64 + t0);
                float4 wb = *(const float4*)(w1 + k*64 + t0);
                float4 wc = *(const float4*)(w2 + k*64 + t0);
                float4 wd = *(const float4*)(w3 + k*64 + t0);
                FMA4(f, dk, wa); FMA4(f, ck, wb);
                FMA4(g, dk, wc); FMA4(g, ck, wd);
            }

            // ---- z = tanh(f)*sigmoid(g) ----
            float z[4];
            #pragma unroll
            for (int j = 0; j < 4; ++j)
                z[j] = tanhf(f[j]) * (1.f / (1.f + __expf(-g[j])));
            *(float4*)(zs + sp*CURP + t0) = make_float4(z[0], z[1], z[2], z[3]);
            CBAR();   // all f/g reads of del[i] and cur done; z visible

            // ---- snapshot pre-update current into dead del[i] slot ----
            {
                float4 c4 = *(const float4*)(cur + sp*CURP + t0);
                *(float4*)(del + (i*TILE + sp)*CURP + t0) = c4;
            }

            // ---- res + skip GEMMs ----
            float r[4];
            #pragma unroll
            for (int j = 0; j < 4; ++j) r[j] = bia[128 + t0 + j];
            const float* zrow = zs + sp*CURP;
            #pragma unroll 8
            for (int k = 0; k < 64; ++k) {
                float zk = zrow[k];
                float4 wv = *(const float4*)(wrs + k*64 + t0);
                FMA4(r, zk, wv);
                const float* wsk = wst + k*96 + ts;
                #pragma unroll
                for (int j = 0; j < 6; ++j) ssum[j] += zk * wsk[j];
            }
            #pragma unroll
            for (int j = 0; j < 6; ++j) ssum[j] += bia[192 + ts + j];

            // ---- residual update (owner-exclusive) ----
            {
                float4 c4 = *(float4*)(cur + sp*CURP + t0);
                c4.x += 0.3f*r[0]; c4.y += 0.3f*r[1];
                c4.z += 0.3f*r[2]; c4.w += 0.3f*r[3];
                *(float4*)(cur + sp*CURP + t0) = c4;
            }
        }

        // ---- head ----
        CBAR();
        #pragma unroll
        for (int j = 0; j < 6; ++j)
            ssm[sp*SSP + ts + j] = fmaxf(ssum[j], 0.f);
        // stage head1_w transposed into w0 region (9216 floats)
        for (int idx = tid; idx < NSKIP*NSKIP; idx += 256) {
            int k = idx / 96, t = idx - k*96;
            w0[idx] = h1w[t*96 + k];
        }
        CBAR();
        {
            float a[6];
            #pragma unroll
            for (int j = 0; j < 6; ++j) a[j] = h1b[ts + j];
            #pragma unroll 4
            for (int k = 0; k < 96; ++k) {
                float u = ssm[sp*SSP + k];
                const float* wk = w0 + k*96 + ts;
                #pragma unroll
                for (int j = 0; j < 6; ++j) a[j] += u * wk[j];
            }
            #pragma unroll
            for (int j = 0; j < 6; ++j)
                hsm[sp*SSP + ts + j] = fmaxf(a[j], 0.f);
        }
        CBAR();
        if (tid < 32) {
            int s = tid >> 1, jj = tid & 1;
            float a = h2b[jj];
            #pragma unroll 4
            for (int k = 0; k < 96; ++k)
                a += hsm[s*SSP + k] * h2w[jj*96 + k];
            out[(bbase + s)*2 + jj] = a;
        }
    } else {
        // =================== SHIFT GROUP (128 threads) =====================
        // dst[n] = src[n+1] over this CTA's flat 1047552-float region.
        const int st = tid - 256;                 // 0..127
        const float* src = buf  + region;
        float*       dst = nbuf + region;
        const bool lastcta = (blockIdx.x == (NBATCH/TILE) - 1);

        for (int it = 0; it < 256; ++it) {
            int m = st + it*128;
            bool valid = (m < NC32);
            int mm = valid ? m : (NC32 - 1);
            const float4* s4 = (const float4*)src + (size_t)mm*8;
            float4 A0 = s4[0], A1 = s4[1], A2 = s4[2], A3 = s4[3];
            float4 A4 = s4[4], A5 = s4[5], A6 = s4[6], A7 = s4[7];
            float nxt = __shfl_down_sync(0xffffffffu, A0.x, 1);
            if (lane == 31) {
                size_t ni = (size_t)mm*32 + 32;
                if (lastcta && ni >= (size_t)REGF) ni = REGF - 1;
                nxt = src[ni];
            }
            if (valid) {
                float4* d4 = (float4*)dst + (size_t)mm*8;
                d4[0] = make_float4(A0.y, A0.z, A0.w, A1.x);
                d4[1] = make_float4(A1.y, A1.z, A1.w, A2.x);
                d4[2] = make_float4(A2.y, A2.z, A2.w, A3.x);
                d4[3] = make_float4(A3.y, A3.z, A3.w, A4.x);
                d4[4] = make_float4(A4.y, A4.z, A4.w, A5.x);
                d4[5] = make_float4(A5.y, A5.z, A5.w, A6.x);
                d4[6] = make_float4(A6.y, A6.z, A6.w, A7.x);
                d4[7] = make_float4(A7.y, A7.z, A7.w, nxt);
            }
        }
    }

    // ================= JOIN + SCATTER (all 384 threads) ====================
    __syncthreads();   // block-scope fence: smem snapshots + nbuf writes ordered
    for (int idx = tid; idx < NBLK*TILE*NCH; idx += 384) {
        int i = idx >> 10, r = idx & 1023;
        int s = r >> 6, c = r & 63;
        int j = (2 << i) - 2;                      // 2^(i+1)-2
        nbuf[region + (size_t)(s*NCH + c)*NCOLS + j] =
            del[(i*TILE + s)*CURP + c];
    }
}

extern "C" void kernel_launch(void* const* d_in, const int* in_sizes, int n_in,
                              void* d_out, int out_size)
{
    const float* x     = (const float*)d_in[0];
    const float* buf   = (const float*)d_in[1];
    const float* inp_w = (const float*)d_in[2];
    const float* inp_b = (const float*)d_in[3];
    const float* fw0   = (const float*)d_in[4];
    const float* fw1   = (const float*)d_in[5];
    const float* fb    = (const float*)d_in[6];
    const float* gw0   = (const float*)d_in[7];
    const float* gw1   = (const float*)d_in[8];
    const float* gb    = (const float*)d_in[9];
    const float* rw    = (const float*)d_in[10];
    const float* rb    = (const float*)d_in[11];
    const float* sw    = (const float*)d_in[12];
    const float* sb    = (const float*)d_in[13];
    const float* h1w   = (const float*)d_in[14];
    const float* h1b   = (const float*)d_in[15];
    const float* h2w   = (const float*)d_in[16];
    const float* h2b   = (const float*)d_in[17];

    float* out  = (float*)d_out;            // (2048, 2)
    float* nbuf = out + NBATCH*2;           // (2048, 64, 1023)

    const int smem_bytes =
        (TILE*CURP*2 + NBLK*TILE*CURP + 5*4096 + 6144 + 288 + 2*TILE*SSP)
        * (int)sizeof(float);               // 172672 B
    cudaFuncSetAttribute(wn_fused, cudaFuncAttributeMaxDynamicSharedMemorySize,
                         smem_bytes);

    wn_fused<<<NBATCH/TILE, 384, smem_bytes>>>(
        x, buf, inp_w, inp_b, fw0, fw1, fb, gw0, gw1, gb,
        rw, rb, sw, sb, h1w, h1b, h2w, h2b, out, nbuf);
}